// round 2
// baseline (speedup 1.0000x reference)
#include <cuda_runtime.h>

// DistMaps: out[b,g,r,c] = tanh(2*sqrt(min_p d2)) over 24 clicks per (b,g) group,
// d2 = ((r-pr)/5)^2 + ((c-pc)/5)^2, invalid clicks (max(pr,pc)<0) -> 1e6.
// x input (d_in[0]) is shape-only; output depends only on coords (d_in[1]).
//
// R2: 4x4 pixel patch per thread (8-row x 512-col tile per 256-thread block)
// to amortize fixed per-warp overhead, which dominated R1 (issue-bound, 70.8%).

namespace {

constexpr int   H         = 512;
constexpr int   W         = 512;
constexpr int   P         = 24;      // clicks per group
constexpr int   TROWS     = 8;       // rows per block tile
constexpr float INV_SCALE = 0.2f;    // 1 / (NORM_RADIUS * SPATIAL_SCALE)
// For d2 >= 41: x = 2*sqrt(d2) >= 12.8, 1-tanh(x) ~ 1.5e-11 << 2^-25,
// so tanhf rounds to exactly 1.0f in both reference and kernel. Safe cull bound.
constexpr float CULL_D2   = 41.0f;

__device__ __forceinline__ float tanh_2sqrt(float q) {
    // tanh(2*sqrt(q)) = (1 - e^{-4s}) / (1 + e^{-4s}), s = sqrt(q)
    float s = sqrtf(q);
    float u = __expf(-4.0f * s);
    return __fdividef(1.0f - u, 1.0f + u);
}

__global__ __launch_bounds__(256, 4) void distmaps_kernel(
    const float* __restrict__ coords,   // [B, 48, 3] (row, col, _)
    float*       __restrict__ out)      // [B, 2, H, W]
{
    __shared__ float s_prs[P];   // scaled click row
    __shared__ float s_pcs[P];   // scaled click col
    __shared__ int   s_n;

    const int tile = blockIdx.x;     // 0..63  (8-row tile index)
    const int bg   = blockIdx.y;     // 0..2B-1
    const int tid  = threadIdx.x;    // 0..255

    const int row0t = tile * TROWS;                // tile base row
    const int cq    = (tid & 127) * 4;             // this thread's base column
    const int r0    = row0t + ((tid >> 7) << 2);   // this thread's base row (4 rows)

    // Warp 0: cull clicks against this 8-row tile, compact survivors.
    if (tid < 32) {
        bool  near = false;
        float prs = 0.0f, pcs = 0.0f;
        if (tid < P) {
            const float* cp = coords + (size_t)(bg * P + tid) * 3;
            float pr = cp[0];
            float pc = cp[1];
            bool valid = fmaxf(pr, pc) >= 0.0f;    // invalid iff both coords < 0
            // closest row of the tile to the click
            float rcl = fminf(fmaxf(pr, (float)row0t), (float)(row0t + TROWS - 1));
            float drs = (rcl - pr) * INV_SCALE;
            near = valid && (drs * drs < CULL_D2);
            prs = pr * INV_SCALE;
            pcs = pc * INV_SCALE;
        }
        unsigned mask = __ballot_sync(0xffffffffu, near);
        if (near) {
            int pos = __popc(mask & ((1u << tid) - 1u));
            s_prs[pos] = prs;
            s_pcs[pos] = pcs;
        }
        if (tid == 0) s_n = __popc(mask);
    }
    __syncthreads();

    const int n = s_n;

    // Scaled row / column coordinates owned by this thread.
    const float rs0 = (float)(r0 + 0) * INV_SCALE;
    const float rs1 = (float)(r0 + 1) * INV_SCALE;
    const float rs2 = (float)(r0 + 2) * INV_SCALE;
    const float rs3 = (float)(r0 + 3) * INV_SCALE;
    const float a0  = (float)(cq + 0) * INV_SCALE;
    const float a1  = (float)(cq + 1) * INV_SCALE;
    const float a2  = (float)(cq + 2) * INV_SCALE;
    const float a3  = (float)(cq + 3) * INV_SCALE;

    // 4 rows x 4 cols of running minima, clamped at CULL_D2 (>=41 -> exactly 1.0f).
    float q[4][4];
#pragma unroll
    for (int i = 0; i < 4; ++i)
#pragma unroll
        for (int j = 0; j < 4; ++j) q[i][j] = CULL_D2;

    for (int p = 0; p < n; ++p) {
        const float prs = s_prs[p];   // LDS broadcast
        const float pcs = s_pcs[p];
        float dr0 = rs0 - prs, dr1 = rs1 - prs, dr2_ = rs2 - prs, dr3 = rs3 - prs;
        float e0 = dr0 * dr0, e1 = dr1 * dr1, e2 = dr2_ * dr2_, e3 = dr3 * dr3;
        float dc0 = a0 - pcs, dc1 = a1 - pcs, dc2 = a2 - pcs, dc3 = a3 - pcs;

        q[0][0] = fminf(q[0][0], fmaf(dc0, dc0, e0));
        q[0][1] = fminf(q[0][1], fmaf(dc1, dc1, e0));
        q[0][2] = fminf(q[0][2], fmaf(dc2, dc2, e0));
        q[0][3] = fminf(q[0][3], fmaf(dc3, dc3, e0));
        q[1][0] = fminf(q[1][0], fmaf(dc0, dc0, e1));
        q[1][1] = fminf(q[1][1], fmaf(dc1, dc1, e1));
        q[1][2] = fminf(q[1][2], fmaf(dc2, dc2, e1));
        q[1][3] = fminf(q[1][3], fmaf(dc3, dc3, e1));
        q[2][0] = fminf(q[2][0], fmaf(dc0, dc0, e2));
        q[2][1] = fminf(q[2][1], fmaf(dc1, dc1, e2));
        q[2][2] = fminf(q[2][2], fmaf(dc2, dc2, e2));
        q[2][3] = fminf(q[2][3], fmaf(dc3, dc3, e2));
        q[3][0] = fminf(q[3][0], fmaf(dc0, dc0, e3));
        q[3][1] = fminf(q[3][1], fmaf(dc1, dc1, e3));
        q[3][2] = fminf(q[3][2], fmaf(dc2, dc2, e3));
        q[3][3] = fminf(q[3][3], fmaf(dc3, dc3, e3));
    }

    // Saturation check: if every lane's 16 minima are clamped, whole warp writes 1.0.
    float qmin = CULL_D2;
#pragma unroll
    for (int i = 0; i < 4; ++i)
#pragma unroll
        for (int j = 0; j < 4; ++j) qmin = fminf(qmin, q[i][j]);

    float* obase = out + ((size_t)bg * H + r0) * W + cq;

    if (__all_sync(0xffffffffu, qmin >= CULL_D2)) {
        const float4 ones = make_float4(1.0f, 1.0f, 1.0f, 1.0f);
#pragma unroll
        for (int i = 0; i < 4; ++i)
            *reinterpret_cast<float4*>(obase + (size_t)i * W) = ones;
    } else {
#pragma unroll
        for (int i = 0; i < 4; ++i) {
            float4 r;
            r.x = tanh_2sqrt(q[i][0]);
            r.y = tanh_2sqrt(q[i][1]);
            r.z = tanh_2sqrt(q[i][2]);
            r.w = tanh_2sqrt(q[i][3]);
            *reinterpret_cast<float4*>(obase + (size_t)i * W) = r;
        }
    }
}

}  // namespace

extern "C" void kernel_launch(void* const* d_in, const int* in_sizes, int n_in,
                              void* d_out, int out_size) {
    // d_in[0]: x [B,3,512,512] f32 (unused), d_in[1]: coords [B,48,3] f32
    const float* coords = (const float*)d_in[1];
    float* out = (float*)d_out;

    const int B = in_sizes[1] / (48 * 3);   // 8
    dim3 grid(H / TROWS, B * 2);
    distmaps_kernel<<<grid, 256>>>(coords, out);
}

// round 3
// speedup vs baseline: 1.1133x; 1.1133x over previous
#include <cuda_runtime.h>

// DistMaps: out[b,g,r,c] = tanh(2*sqrt(min_p d2)) over 24 clicks per (b,g) group,
// d2 = ((r-pr)/5)^2 + ((c-pc)/5)^2, invalid clicks (max(pr,pc)<0) -> 1e6.
// x input (d_in[0]) is shape-only; output depends only on coords (d_in[1]).
//
// R3: R2 was epilogue-bound (IEEE sqrtf + __expf + __fdividef ~ 15 instr/px).
// Replace with sqrt.approx + tanh.approx (3 instr/px), per-row saturation vote,
// row-outer loop to cut register pressure and lift occupancy.

namespace {

constexpr int   H         = 512;
constexpr int   W         = 512;
constexpr int   P         = 24;      // clicks per group
constexpr int   TROWS     = 8;       // rows per block tile
constexpr float INV_SCALE = 0.2f;    // 1 / (NORM_RADIUS * SPATIAL_SCALE)
// For d2 >= 41: x = 2*sqrt(d2) >= 12.8, 1-tanh(x) ~ 1.5e-11 << 2^-25,
// so tanh rounds to exactly 1.0f in both reference and kernel. Safe cull bound.
constexpr float CULL_D2   = 41.0f;

__device__ __forceinline__ float tanh_2sqrt_fast(float q) {
    float s, t;
    asm("sqrt.approx.f32 %0, %1;" : "=f"(s) : "f"(q));
    s = 2.0f * s;
    asm("tanh.approx.f32 %0, %1;" : "=f"(t) : "f"(s));
    return t;
}

__global__ __launch_bounds__(256, 6) void distmaps_kernel(
    const float* __restrict__ coords,   // [B, 48, 3] (row, col, _)
    float*       __restrict__ out)      // [B, 2, H, W]
{
    __shared__ float s_prs[P];   // scaled click row
    __shared__ float s_pcs[P];   // scaled click col
    __shared__ int   s_n;

    const int tile = blockIdx.x;     // 0..63  (8-row tile index)
    const int bg   = blockIdx.y;     // 0..2B-1
    const int tid  = threadIdx.x;    // 0..255

    const int row0t = tile * TROWS;                // tile base row
    const int cq    = (tid & 127) * 4;             // this thread's base column
    const int r0    = row0t + ((tid >> 7) << 2);   // this thread's base row (4 rows)

    // Warp 0: cull clicks against this 8-row tile, compact survivors.
    if (tid < 32) {
        bool  near = false;
        float prs = 0.0f, pcs = 0.0f;
        if (tid < P) {
            const float* cp = coords + (size_t)(bg * P + tid) * 3;
            float pr = cp[0];
            float pc = cp[1];
            bool valid = fmaxf(pr, pc) >= 0.0f;    // invalid iff both coords < 0
            // closest row of the tile to the click
            float rcl = fminf(fmaxf(pr, (float)row0t), (float)(row0t + TROWS - 1));
            float drs = (rcl - pr) * INV_SCALE;
            near = valid && (drs * drs < CULL_D2);
            prs = pr * INV_SCALE;
            pcs = pc * INV_SCALE;
        }
        unsigned mask = __ballot_sync(0xffffffffu, near);
        if (near) {
            int pos = __popc(mask & ((1u << tid) - 1u));
            s_prs[pos] = prs;
            s_pcs[pos] = pcs;
        }
        if (tid == 0) s_n = __popc(mask);
    }
    __syncthreads();

    const int n = s_n;

    const float a0 = (float)(cq + 0) * INV_SCALE;
    const float a1 = (float)(cq + 1) * INV_SCALE;
    const float a2 = (float)(cq + 2) * INV_SCALE;
    const float a3 = (float)(cq + 3) * INV_SCALE;

    float* obase = out + ((size_t)bg * H + r0) * W + cq;

#pragma unroll
    for (int i = 0; i < 4; ++i) {
        const float rsi = (float)(r0 + i) * INV_SCALE;

        // Running minima for 4 columns of this row, clamped at CULL_D2.
        float q0 = CULL_D2, q1 = CULL_D2, q2 = CULL_D2, q3 = CULL_D2;

        for (int p = 0; p < n; ++p) {
            const float prs = s_prs[p];   // LDS broadcast
            const float pcs = s_pcs[p];
            const float dr = rsi - prs;
            const float e  = dr * dr;
            float d;
            d = a0 - pcs; q0 = fminf(q0, fmaf(d, d, e));
            d = a1 - pcs; q1 = fminf(q1, fmaf(d, d, e));
            d = a2 - pcs; q2 = fminf(q2, fmaf(d, d, e));
            d = a3 - pcs; q3 = fminf(q3, fmaf(d, d, e));
        }

        const float rmin = fminf(fminf(q0, q1), fminf(q2, q3));
        float4 r;
        if (__all_sync(0xffffffffu, rmin >= CULL_D2)) {
            // Whole warp-row saturated: tanh == 1.0f exactly, skip MUFU.
            r = make_float4(1.0f, 1.0f, 1.0f, 1.0f);
        } else {
            r.x = tanh_2sqrt_fast(q0);
            r.y = tanh_2sqrt_fast(q1);
            r.z = tanh_2sqrt_fast(q2);
            r.w = tanh_2sqrt_fast(q3);
        }
        *reinterpret_cast<float4*>(obase + (size_t)i * W) = r;
    }
}

}  // namespace

extern "C" void kernel_launch(void* const* d_in, const int* in_sizes, int n_in,
                              void* d_out, int out_size) {
    // d_in[0]: x [B,3,512,512] f32 (unused), d_in[1]: coords [B,48,3] f32
    const float* coords = (const float*)d_in[1];
    float* out = (float*)d_out;

    const int B = in_sizes[1] / (48 * 3);   // 8
    dim3 grid(H / TROWS, B * 2);
    distmaps_kernel<<<grid, 256>>>(coords, out);
}